// round 2
// baseline (speedup 1.0000x reference)
#include <cuda_runtime.h>
#include <math.h>

#define B_WIN 2048
#define N_TOK 64
#define DIMC  512
#define NH    16
#define HD    32
#define PP    16
#define MQ    (B_WIN * N_TOK)   // 131072
#define MP    (B_WIN * PP)      // 32768

// ---------------- scratch (allocation-free rule: __device__ globals) --------
__device__ float g_Q [(size_t)MQ * DIMC];   // scaled q, [B*N, DIM]
__device__ float g_XK[(size_t)MP * DIMC];   // w_k @ x,  [B*P, DIM]
__device__ float g_XV[(size_t)MP * DIMC];
__device__ float g_KP[(size_t)MP * DIMC];   // projected k, [B*P, DIM] (h-major cols)
__device__ float g_VP[(size_t)MP * DIMC];
__device__ float g_O [(size_t)MQ * DIMC];   // attention output before final proj
__device__ float g_sk[PP];
__device__ float g_sv[PP];

// ---------------- tiny: row sums of w_k / w_v (for folded bias) ------------
__global__ void rowsum_kernel(const float* __restrict__ w_k,
                              const float* __restrict__ w_v) {
    int p = threadIdx.x;
    if (p < PP) {
        float s1 = 0.f, s2 = 0.f;
        for (int n = 0; n < N_TOK; n++) { s1 += w_k[p * N_TOK + n]; s2 += w_v[p * N_TOK + n]; }
        g_sk[p] = s1;
        g_sv[p] = s2;
    }
}

// ---------------- token projection: xk[b,p,c] = sum_n w_k[p,n] * x[b,n,c] --
__global__ __launch_bounds__(512) void xproj_kernel(const float* __restrict__ x,
                                                    const float* __restrict__ w_k,
                                                    const float* __restrict__ w_v) {
    __shared__ float sk[PP * N_TOK];
    __shared__ float sv[PP * N_TOK];
    int b = blockIdx.x;
    for (int i = threadIdx.x; i < PP * N_TOK; i += blockDim.x) {
        sk[i] = w_k[i];
        sv[i] = w_v[i];
    }
    __syncthreads();
    int c = threadIdx.x;  // 512 threads = DIMC
    const float* xb = x + (size_t)b * N_TOK * DIMC + c;
    float ak[PP], av[PP];
#pragma unroll
    for (int p = 0; p < PP; p++) { ak[p] = 0.f; av[p] = 0.f; }
    for (int n = 0; n < N_TOK; n++) {
        float xv = xb[(size_t)n * DIMC];
#pragma unroll
        for (int p = 0; p < PP; p++) {
            ak[p] += sk[p * N_TOK + n] * xv;
            av[p] += sv[p * N_TOK + n] * xv;
        }
    }
#pragma unroll
    for (int p = 0; p < PP; p++) {
        g_XK[((size_t)b * PP + p) * DIMC + c] = ak[p];
        g_XV[((size_t)b * PP + p) * DIMC + c] = av[p];
    }
}

// ---------------- generic SGEMM: C = (A@B + srow[r%16]*biascol[c]) * alpha --
// A [M,K] row-major (lda=K), B row-major with ldb, C [M,N] row-major.
// M % 128 == 0, N % 128 == 0, K % 8 == 0 (guaranteed by shapes here).
__global__ __launch_bounds__(256) void sgemm_kernel(
    const float* __restrict__ A, const float* __restrict__ B,
    float* __restrict__ C, int M, int N, int K, int ldb,
    const float* __restrict__ biascol, const float* __restrict__ srow,
    float alpha) {
    const int BK = 8;
    __shared__ float As[BK][128];
    __shared__ float Bs[BK][128];

    int tid = threadIdx.x;
    int bm = blockIdx.y, bn = blockIdx.x;
    int tx = tid & 15, ty = tid >> 4;

    float acc[8][8];
#pragma unroll
    for (int i = 0; i < 8; i++)
#pragma unroll
        for (int j = 0; j < 8; j++) acc[i][j] = 0.f;

    const float* Ab = A + (size_t)bm * 128 * K;
    const float* Bb = B + (size_t)bn * 128;

    int arow = tid >> 1, acol = (tid & 1) * 4;
    int brow = tid >> 5, bcol = (tid & 31) * 4;

    for (int k0 = 0; k0 < K; k0 += BK) {
        float4 a4 = *(const float4*)(Ab + (size_t)arow * K + k0 + acol);
        As[acol + 0][arow] = a4.x;
        As[acol + 1][arow] = a4.y;
        As[acol + 2][arow] = a4.z;
        As[acol + 3][arow] = a4.w;
        float4 b4 = *(const float4*)(Bb + (size_t)(k0 + brow) * ldb + bcol);
        *(float4*)&Bs[brow][bcol] = b4;
        __syncthreads();
#pragma unroll
        for (int kk = 0; kk < BK; kk++) {
            float a[8], b[8];
            *(float4*)&a[0] = *(float4*)&As[kk][ty * 8];
            *(float4*)&a[4] = *(float4*)&As[kk][ty * 8 + 4];
            *(float4*)&b[0] = *(float4*)&Bs[kk][tx * 8];
            *(float4*)&b[4] = *(float4*)&Bs[kk][tx * 8 + 4];
#pragma unroll
            for (int i = 0; i < 8; i++)
#pragma unroll
                for (int j = 0; j < 8; j++) acc[i][j] += a[i] * b[j];
        }
        __syncthreads();
    }

#pragma unroll
    for (int i = 0; i < 8; i++) {
        int rg = bm * 128 + ty * 8 + i;
        float sr = srow ? srow[rg & 15] : 1.f;
#pragma unroll
        for (int j = 0; j < 8; j++) {
            int cg = bn * 128 + tx * 8 + j;
            float bc = biascol ? biascol[cg] : 0.f;
            C[(size_t)rg * N + cg] = (acc[i][j] + sr * bc) * alpha;
        }
    }
}

// ---------------- attention: per-window, per-(head,row) softmax over P=16 --
__global__ __launch_bounds__(256) void attn_kernel(const float* __restrict__ biastab) {
    __shared__ float skp[NH * PP * HD];  // 32 KB
    __shared__ float svp[NH * PP * HD];  // 32 KB
    int b = blockIdx.x;

    for (int i = threadIdx.x; i < NH * PP * HD; i += blockDim.x) {
        int h = i / (PP * HD);
        int p = (i / HD) % PP;
        int d = i % HD;
        size_t src = ((size_t)b * PP + p) * DIMC + h * HD + d;
        skp[i] = g_KP[src];
        svp[i] = g_VP[src];
    }
    __syncthreads();

    for (int task = threadIdx.x; task < NH * N_TOK; task += blockDim.x) {
        int h = task / N_TOK;
        int n = task % N_TOK;
        const float* qrow = g_Q + ((size_t)b * N_TOK + n) * DIMC + h * HD;
        float q[HD];
#pragma unroll
        for (int d = 0; d < HD; d += 4) {
            float4 v = *(const float4*)(qrow + d);
            q[d] = v.x; q[d + 1] = v.y; q[d + 2] = v.z; q[d + 3] = v.w;
        }
        int yn = n >> 3, xn = n & 7;
        float logit[PP];
#pragma unroll
        for (int p = 0; p < PP; p++) {
            const float* kr = &skp[(h * PP + p) * HD];
            float s = 0.f;
#pragma unroll
            for (int d = 0; d < HD; d++) s += q[d] * kr[d];
            int yp = p >> 3, xp = p & 7;
            int idx = (yn - yp + 7) * 15 + (xn - xp + 7);
            logit[p] = s + biastab[idx * NH + h];
        }
        float m = logit[0];
#pragma unroll
        for (int p = 1; p < PP; p++) m = fmaxf(m, logit[p]);
        float sum = 0.f;
#pragma unroll
        for (int p = 0; p < PP; p++) {
            float e = __expf(logit[p] - m);
            logit[p] = e;
            sum += e;
        }
        float inv = 1.f / sum;
        float o[HD];
#pragma unroll
        for (int d = 0; d < HD; d++) o[d] = 0.f;
#pragma unroll
        for (int p = 0; p < PP; p++) {
            float w = logit[p] * inv;
            const float* vr = &svp[(h * PP + p) * HD];
#pragma unroll
            for (int d = 0; d < HD; d++) o[d] += w * vr[d];
        }
        float* orow = g_O + ((size_t)b * N_TOK + n) * DIMC + h * HD;
#pragma unroll
        for (int d = 0; d < HD; d += 4) {
            float4 v = make_float4(o[d], o[d + 1], o[d + 2], o[d + 3]);
            *(float4*)(orow + d) = v;
        }
    }
}

// ---------------------------------------------------------------------------
extern "C" void kernel_launch(void* const* d_in, const int* in_sizes, int n_in,
                              void* d_out, int out_size) {
    const float* x      = (const float*)d_in[0];
    const float* w_qkv  = (const float*)d_in[1];
    const float* b_qkv  = (const float*)d_in[2];
    const float* w_proj = (const float*)d_in[3];
    const float* b_proj = (const float*)d_in[4];
    const float* w_k    = (const float*)d_in[5];
    const float* w_v    = (const float*)d_in[6];
    const float* btab   = (const float*)d_in[7];
    float* out = (float*)d_out;

    float *Q, *XK, *XV, *KP, *VP, *O, *sk, *sv;
    cudaGetSymbolAddress((void**)&Q,  g_Q);
    cudaGetSymbolAddress((void**)&XK, g_XK);
    cudaGetSymbolAddress((void**)&XV, g_XV);
    cudaGetSymbolAddress((void**)&KP, g_KP);
    cudaGetSymbolAddress((void**)&VP, g_VP);
    cudaGetSymbolAddress((void**)&O,  g_O);
    cudaGetSymbolAddress((void**)&sk, g_sk);
    cudaGetSymbolAddress((void**)&sv, g_sv);

    const float scale = 0.17677669529663687f;  // 32^-0.5

    rowsum_kernel<<<1, 32>>>(w_k, w_v);
    xproj_kernel<<<B_WIN, 512>>>(x, w_k, w_v);

    // Q = (x @ Wq + bq) * scale      [131072, 512], B cols 0..511 of w_qkv
    sgemm_kernel<<<dim3(DIMC / 128, MQ / 128), 256>>>(
        x, w_qkv, Q, MQ, DIMC, DIMC, 3 * DIMC, b_qkv, nullptr, scale);

    // KP = XK @ Wk + s_k[p] * bk     [32768, 512]
    sgemm_kernel<<<dim3(DIMC / 128, MP / 128), 256>>>(
        XK, w_qkv + DIMC, KP, MP, DIMC, DIMC, 3 * DIMC, b_qkv + DIMC, sk, 1.f);

    // VP = XV @ Wv + s_v[p] * bv
    sgemm_kernel<<<dim3(DIMC / 128, MP / 128), 256>>>(
        XV, w_qkv + 2 * DIMC, VP, MP, DIMC, DIMC, 3 * DIMC, b_qkv + 2 * DIMC, sv, 1.f);

    attn_kernel<<<B_WIN, 256>>>(btab);

    // out = O @ w_proj + b_proj      [131072, 512]
    sgemm_kernel<<<dim3(DIMC / 128, MQ / 128), 256>>>(
        O, w_proj, out, MQ, DIMC, DIMC, DIMC, b_proj, nullptr, 1.f);
}

// round 5
// speedup vs baseline: 3.8430x; 3.8430x over previous
#include <cuda_runtime.h>
#include <cuda_fp16.h>
#include <cstdint>
#include <math.h>

#define B_WIN 2048
#define N_TOK 64
#define DIMC  512
#define NH    16
#define HD    32
#define PP    16
#define MQ    (B_WIN * N_TOK)   // 131072
#define MP    (B_WIN * PP)      // 32768

// ---------------- scratch (allocation-free rule: __device__ globals) --------
__device__ float  g_Q  [(size_t)MQ * DIMC];   // fp32 (attn input)
__device__ __half g_x16[(size_t)MQ * DIMC];
__device__ __half g_XK [(size_t)MP * DIMC];
__device__ __half g_XV [(size_t)MP * DIMC];
__device__ float  g_KP [(size_t)MP * DIMC];
__device__ float  g_VP [(size_t)MP * DIMC];
__device__ __half g_O16[(size_t)MQ * DIMC];
__device__ __half g_WT [4 * DIMC * DIMC];     // transposed weights [N,K] K-major fp16
__device__ float  g_sk[PP];
__device__ float  g_sv[PP];

// ======================= PTX helpers =======================================
__device__ __forceinline__ uint32_t smem_u32(const void* p) {
    uint32_t a;
    asm("{ .reg .u64 t; cvta.to.shared.u64 t, %1; cvt.u32.u64 %0, t; }" : "=r"(a) : "l"(p));
    return a;
}
__device__ __forceinline__ void cp16(uint32_t saddr, const void* g) {
    asm volatile("cp.async.cg.shared.global [%0], [%1], 16;" :: "r"(saddr), "l"(g));
}
__device__ __forceinline__ void cp_commit() { asm volatile("cp.async.commit_group;"); }
__device__ __forceinline__ void cp_wait1()  { asm volatile("cp.async.wait_group 1;"); }
__device__ __forceinline__ void ldsm_x4(uint32_t* r, uint32_t addr) {
    asm volatile("ldmatrix.sync.aligned.m8n8.x4.shared.b16 {%0,%1,%2,%3}, [%4];"
        : "=r"(r[0]), "=r"(r[1]), "=r"(r[2]), "=r"(r[3]) : "r"(addr));
}
__device__ __forceinline__ void mma16816(float* c, const uint32_t* a, const uint32_t* b) {
    asm volatile("mma.sync.aligned.m16n8k16.row.col.f32.f16.f16.f32 "
        "{%0,%1,%2,%3}, {%4,%5,%6,%7}, {%8,%9}, {%0,%1,%2,%3};"
        : "+f"(c[0]), "+f"(c[1]), "+f"(c[2]), "+f"(c[3])
        : "r"(a[0]), "r"(a[1]), "r"(a[2]), "r"(a[3]), "r"(b[0]), "r"(b[1]));
}

// ---------------- fp32 -> fp16 bulk convert --------------------------------
__global__ __launch_bounds__(256) void cvt_kernel(const float4* __restrict__ src,
                                                  uint2* __restrict__ dst, int n4) {
    int i = blockIdx.x * blockDim.x + threadIdx.x;
    if (i < n4) {
        float4 v = src[i];
        __half2 h0 = __floats2half2_rn(v.x, v.y);
        __half2 h1 = __floats2half2_rn(v.z, v.w);
        uint2 o;
        o.x = *reinterpret_cast<uint32_t*>(&h0);
        o.y = *reinterpret_cast<uint32_t*>(&h1);
        dst[i] = o;
    }
}

// ---------------- weight transpose -> fp16 [N,K] ---------------------------
__global__ void transpose_kernel(const float* __restrict__ w_qkv,
                                 const float* __restrict__ w_proj) {
    __shared__ float t[32][33];
    int m = blockIdx.z;
    const float* src = (m < 3) ? w_qkv : w_proj;
    int ld = (m < 3) ? 3 * DIMC : DIMC;
    int coloff = (m < 3) ? m * DIMC : 0;
    int bx = blockIdx.x * 32, by = blockIdx.y * 32;
    int tx = threadIdx.x, ty = threadIdx.y;
#pragma unroll
    for (int i = 0; i < 32; i += 8)
        t[ty + i][tx] = src[(size_t)(by + ty + i) * ld + coloff + bx + tx];
    __syncthreads();
    __half* dst = g_WT + (size_t)m * DIMC * DIMC;
#pragma unroll
    for (int i = 0; i < 32; i += 8)
        dst[(size_t)(bx + ty + i) * DIMC + by + tx] = __float2half_rn(t[tx][ty + i]);
}

// ---------------- row sums of w_k / w_v ------------------------------------
__global__ void rowsum_kernel(const float* __restrict__ w_k,
                              const float* __restrict__ w_v) {
    int p = threadIdx.x;
    if (p < PP) {
        float s1 = 0.f, s2 = 0.f;
        for (int n = 0; n < N_TOK; n++) { s1 += w_k[p * N_TOK + n]; s2 += w_v[p * N_TOK + n]; }
        g_sk[p] = s1;
        g_sv[p] = s2;
    }
}

// ---------------- token projection -> fp16 ---------------------------------
__global__ __launch_bounds__(512) void xproj_kernel(const float* __restrict__ x,
                                                    const float* __restrict__ w_k,
                                                    const float* __restrict__ w_v) {
    __shared__ float sk[PP * N_TOK];
    __shared__ float sv[PP * N_TOK];
    int b = blockIdx.x;
    for (int i = threadIdx.x; i < PP * N_TOK; i += blockDim.x) {
        sk[i] = w_k[i];
        sv[i] = w_v[i];
    }
    __syncthreads();
    int c = threadIdx.x;
    const float* xb = x + (size_t)b * N_TOK * DIMC + c;
    float ak[PP], av[PP];
#pragma unroll
    for (int p = 0; p < PP; p++) { ak[p] = 0.f; av[p] = 0.f; }
    for (int n = 0; n < N_TOK; n++) {
        float xv = xb[(size_t)n * DIMC];
#pragma unroll
        for (int p = 0; p < PP; p++) {
            ak[p] += sk[p * N_TOK + n] * xv;
            av[p] += sv[p * N_TOK + n] * xv;
        }
    }
#pragma unroll
    for (int p = 0; p < PP; p++) {
        g_XK[((size_t)b * PP + p) * DIMC + c] = __float2half_rn(ak[p]);
        g_XV[((size_t)b * PP + p) * DIMC + c] = __float2half_rn(av[p]);
    }
}

// =================== mma.sync fp16 GEMM ====================================
// C[M,512] = A16[M,512] @ Bt16[512,512]^T ; C = (acc + srow[r%16]*biascol[c])*alpha
// CTA tile 128x128, BK=32, 3-stage cp.async pipeline, 8 warps at 32x64.
// smem rows padded to 40 halfs (80 B) -> conflict-free ldmatrix.
#define PADK   40
#define STAGEB 20480     // (128*40 + 128*40) halfs * 2B
#define DYN_SMEM (3 * STAGEB)

__global__ __launch_bounds__(256, 2) void tgemm_kernel(
    const __half* __restrict__ A, const __half* __restrict__ Bt,
    float* __restrict__ C,
    const float* __restrict__ biascol, const float* __restrict__ srow, float alpha) {
    extern __shared__ __align__(16) char smem[];
    uint32_t sb = smem_u32(smem);

    int tid = threadIdx.x;
    int wid = tid >> 5, lane = tid & 31;
    int bn = blockIdx.x, bm = blockIdx.y;

    const __half* Ag = A + (size_t)bm * 128 * DIMC;
    const __half* Bg = Bt + (size_t)bn * 128 * DIMC;

    // global->smem: 512 chunks of 16B per operand per stage, 2 per thread
    int grow = tid >> 2, gcol = tid & 3;   // chunk c=tid: row=c>>2, col=c&3 (+64 rows for c+256)
    auto load_stage = [&](int kc, int st) {
        uint32_t a0 = sb + st * STAGEB;
        uint32_t b0 = a0 + 10240;
        const __half* Agk = Ag + kc * 32;
        const __half* Bgk = Bg + kc * 32;
#pragma unroll
        for (int i = 0; i < 2; i++) {
            int row = grow + i * 64;
            cp16(a0 + row * 80 + gcol * 16, Agk + (size_t)row * DIMC + gcol * 8);
            cp16(b0 + row * 80 + gcol * 16, Bgk + (size_t)row * DIMC + gcol * 8);
        }
    };

    float acc[2][8][4];
#pragma unroll
    for (int mt = 0; mt < 2; mt++)
#pragma unroll
        for (int nt = 0; nt < 8; nt++)
#pragma unroll
            for (int e = 0; e < 4; e++) acc[mt][nt][e] = 0.f;

    int warp_m = wid & 3, warp_n = wid >> 2;
    int arow = (lane & 7) + ((lane >> 3) & 1) * 8;   // A ldmatrix row select
    int achk = lane >> 4;                            // A k-chunk select
    int brow = (lane & 7) + ((lane >> 4) & 1) * 8;   // B ldmatrix row select
    int bchk = (lane >> 3) & 1;                      // B k-chunk select

    load_stage(0, 0); cp_commit();
    load_stage(1, 1); cp_commit();

    const int NK = 16;
    for (int kc = 0; kc < NK; kc++) {
        int st = kc % 3;
        cp_wait1();
        __syncthreads();
        if (kc + 2 < NK) load_stage(kc + 2, (kc + 2) % 3);
        cp_commit();

        uint32_t aS = sb + st * STAGEB;
        uint32_t bS = aS + 10240;
#pragma unroll
        for (int ks = 0; ks < 2; ks++) {
            uint32_t af[2][4];
            uint32_t abase = aS + (uint32_t)((warp_m * 32 + arow) * 80 + ks * 32 + achk * 16);
            ldsm_x4(af[0], abase);
            ldsm_x4(af[1], abase + 16 * 80);
            uint32_t bf[8][2];
#pragma unroll
            for (int bt = 0; bt < 4; bt++) {
                uint32_t t[4];
                ldsm_x4(t, bS + (uint32_t)((warp_n * 64 + bt * 16 + brow) * 80 + ks * 32 + bchk * 16));
                bf[2 * bt][0] = t[0]; bf[2 * bt][1] = t[1];
                bf[2 * bt + 1][0] = t[2]; bf[2 * bt + 1][1] = t[3];
            }
#pragma unroll
            for (int mt = 0; mt < 2; mt++)
#pragma unroll
                for (int nt = 0; nt < 8; nt++)
                    mma16816(acc[mt][nt], af[mt], bf[nt]);
        }
        __syncthreads();
    }

    // ---- epilogue ----
    int rbase = bm * 128 + warp_m * 32 + (lane >> 2);
    int cbase = bn * 128 + warp_n * 64 + (lane & 3) * 2;
#pragma unroll
    for (int mt = 0; mt < 2; mt++) {
#pragma unroll
        for (int h = 0; h < 2; h++) {
            int r = rbase + mt * 16 + h * 8;
            float sr = srow ? srow[r & 15] : 1.f;
            float* crow = C + (size_t)r * DIMC;
#pragma unroll
            for (int nt = 0; nt < 8; nt++) {
                int c = cbase + nt * 8;
                float2 o;
                o.x = (acc[mt][nt][h * 2 + 0] + sr * biascol[c]) * alpha;
                o.y = (acc[mt][nt][h * 2 + 1] + sr * biascol[c + 1]) * alpha;
                *(float2*)(crow + c) = o;
            }
        }
    }
}

// ---------------- attention: per-window softmax over P=16, fp16 out --------
__global__ __launch_bounds__(256) void attn_kernel(const float* __restrict__ biastab) {
    __shared__ float skp[NH * PP * HD];
    __shared__ float svp[NH * PP * HD];
    int b = blockIdx.x;

    for (int i = threadIdx.x; i < NH * PP * HD; i += blockDim.x) {
        int h = i / (PP * HD);
        int p = (i / HD) % PP;
        int d = i % HD;
        size_t src = ((size_t)b * PP + p) * DIMC + h * HD + d;
        skp[i] = g_KP[src];
        svp[i] = g_VP[src];
    }
    __syncthreads();

    for (int task = threadIdx.x; task < NH * N_TOK; task += blockDim.x) {
        int h = task / N_TOK;
        int n = task % N_TOK;
        const float* qrow = g_Q + ((size_t)b * N_TOK + n) * DIMC + h * HD;
        float q[HD];
#pragma unroll
        for (int d = 0; d < HD; d += 4) {
            float4 v = *(const float4*)(qrow + d);
            q[d] = v.x; q[d + 1] = v.y; q[d + 2] = v.z; q[d + 3] = v.w;
        }
        int yn = n >> 3, xn = n & 7;
        float logit[PP];
#pragma unroll
        for (int p = 0; p < PP; p++) {
            const float* kr = &skp[(h * PP + p) * HD];
            float s = 0.f;
#pragma unroll
            for (int d = 0; d < HD; d++) s += q[d] * kr[d];
            int yp = p >> 3, xp = p & 7;
            int idx = (yn - yp + 7) * 15 + (xn - xp + 7);
            logit[p] = s + biastab[idx * NH + h];
        }
        float m = logit[0];
#pragma unroll
        for (int p = 1; p < PP; p++) m = fmaxf(m, logit[p]);
        float sum = 0.f;
#pragma unroll
        for (int p = 0; p < PP; p++) {
            float e = __expf(logit[p] - m);
            logit[p] = e;
            sum += e;
        }
        float inv = 1.f / sum;
        float o[HD];
#pragma unroll
        for (int d = 0; d < HD; d++) o[d] = 0.f;
#pragma unroll
        for (int p = 0; p < PP; p++) {
            float w = logit[p] * inv;
            const float* vr = &svp[(h * PP + p) * HD];
#pragma unroll
            for (int d = 0; d < HD; d++) o[d] += w * vr[d];
        }
        __half2* orow = (__half2*)(g_O16 + ((size_t)b * N_TOK + n) * DIMC + h * HD);
#pragma unroll
        for (int d = 0; d < HD; d += 2)
            orow[d >> 1] = __floats2half2_rn(o[d], o[d + 1]);
    }
}

// ---------------------------------------------------------------------------
extern "C" void kernel_launch(void* const* d_in, const int* in_sizes, int n_in,
                              void* d_out, int out_size) {
    const float* x      = (const float*)d_in[0];
    const float* w_qkv  = (const float*)d_in[1];
    const float* b_qkv  = (const float*)d_in[2];
    const float* w_proj = (const float*)d_in[3];
    const float* b_proj = (const float*)d_in[4];
    const float* w_k    = (const float*)d_in[5];
    const float* w_v    = (const float*)d_in[6];
    const float* btab   = (const float*)d_in[7];
    float* out = (float*)d_out;

    float *Q, *KP, *VP, *sk, *sv;
    __half *x16, *XK, *XV, *O16, *WT;
    cudaGetSymbolAddress((void**)&Q,   g_Q);
    cudaGetSymbolAddress((void**)&x16, g_x16);
    cudaGetSymbolAddress((void**)&XK,  g_XK);
    cudaGetSymbolAddress((void**)&XV,  g_XV);
    cudaGetSymbolAddress((void**)&KP,  g_KP);
    cudaGetSymbolAddress((void**)&VP,  g_VP);
    cudaGetSymbolAddress((void**)&O16, g_O16);
    cudaGetSymbolAddress((void**)&WT,  g_WT);
    cudaGetSymbolAddress((void**)&sk,  g_sk);
    cudaGetSymbolAddress((void**)&sv,  g_sv);

    cudaFuncSetAttribute(tgemm_kernel, cudaFuncAttributeMaxDynamicSharedMemorySize, DYN_SMEM);

    const float scale = 0.17677669529663687f;  // 32^-0.5
    const int n4 = MQ * DIMC / 4;

    cvt_kernel<<<(n4 + 255) / 256, 256>>>((const float4*)x, (uint2*)x16, n4);
    transpose_kernel<<<dim3(16, 16, 4), dim3(32, 8)>>>(w_qkv, w_proj);
    rowsum_kernel<<<1, 32>>>(w_k, w_v);
    xproj_kernel<<<B_WIN, 512>>>(x, w_k, w_v);

    // Q = (x @ Wq + bq) * scale
    tgemm_kernel<<<dim3(4, MQ / 128), 256, DYN_SMEM>>>(
        x16, WT + 0 * DIMC * DIMC, Q, b_qkv, nullptr, scale);
    // KP = XK @ Wk + s_k[p] * bk
    tgemm_kernel<<<dim3(4, MP / 128), 256, DYN_SMEM>>>(
        XK, WT + 1 * DIMC * DIMC, KP, b_qkv + DIMC, sk, 1.f);
    // VP = XV @ Wv + s_v[p] * bv
    tgemm_kernel<<<dim3(4, MP / 128), 256, DYN_SMEM>>>(
        XV, WT + 2 * DIMC * DIMC, VP, b_qkv + 2 * DIMC, sv, 1.f);

    attn_kernel<<<B_WIN, 256>>>(btab);

    // out = O @ w_proj + b_proj
    tgemm_kernel<<<dim3(4, MQ / 128), 256, DYN_SMEM>>>(
        O16, WT + 3 * DIMC * DIMC, out, b_proj, nullptr, 1.f);
}

// round 9
// speedup vs baseline: 4.4746x; 1.1643x over previous
#include <cuda_runtime.h>
#include <cuda_fp16.h>
#include <cstdint>
#include <math.h>

#define B_WIN 2048
#define N_TOK 64
#define DIMC  512
#define NH    16
#define HD    32
#define PP    16
#define MQ    (B_WIN * N_TOK)   // 131072
#define MP    (B_WIN * PP)      // 32768

// ---------------- scratch (allocation-free rule: __device__ globals) --------
__device__ __half g_Q16[(size_t)MQ * DIMC];
__device__ __half g_x16[(size_t)MQ * DIMC];
__device__ __half g_XK [(size_t)MP * DIMC];
__device__ __half g_XV [(size_t)MP * DIMC];
__device__ __half g_KP16[(size_t)MP * DIMC];
__device__ __half g_VP16[(size_t)MP * DIMC];
__device__ __half g_O16[(size_t)MQ * DIMC];
__device__ __half g_WT [4 * DIMC * DIMC];     // transposed weights [N,K] K-major fp16
__device__ float  g_sk[PP];
__device__ float  g_sv[PP];

// ======================= PTX helpers =======================================
__device__ __forceinline__ uint32_t smem_u32(const void* p) {
    uint32_t a;
    asm("{ .reg .u64 t; cvta.to.shared.u64 t, %1; cvt.u32.u64 %0, t; }" : "=r"(a) : "l"(p));
    return a;
}
__device__ __forceinline__ void cp16(uint32_t saddr, const void* g) {
    asm volatile("cp.async.cg.shared.global [%0], [%1], 16;" :: "r"(saddr), "l"(g));
}
__device__ __forceinline__ void cp_commit() { asm volatile("cp.async.commit_group;"); }
__device__ __forceinline__ void cp_wait1()  { asm volatile("cp.async.wait_group 1;"); }
__device__ __forceinline__ void cp_wait0()  { asm volatile("cp.async.wait_group 0;"); }
__device__ __forceinline__ void ldsm_x4(uint32_t* r, uint32_t addr) {
    asm volatile("ldmatrix.sync.aligned.m8n8.x4.shared.b16 {%0,%1,%2,%3}, [%4];"
        : "=r"(r[0]), "=r"(r[1]), "=r"(r[2]), "=r"(r[3]) : "r"(addr));
}
__device__ __forceinline__ void mma16816(float* c, const uint32_t* a, const uint32_t* b) {
    asm volatile("mma.sync.aligned.m16n8k16.row.col.f32.f16.f16.f32 "
        "{%0,%1,%2,%3}, {%4,%5,%6,%7}, {%8,%9}, {%0,%1,%2,%3};"
        : "+f"(c[0]), "+f"(c[1]), "+f"(c[2]), "+f"(c[3])
        : "r"(a[0]), "r"(a[1]), "r"(a[2]), "r"(a[3]), "r"(b[0]), "r"(b[1]));
}

// ---------------- weight transpose -> fp16 [N,K] ---------------------------
__global__ void transpose_kernel(const float* __restrict__ w_qkv,
                                 const float* __restrict__ w_proj) {
    __shared__ float t[32][33];
    int m = blockIdx.z;
    const float* src = (m < 3) ? w_qkv : w_proj;
    int ld = (m < 3) ? 3 * DIMC : DIMC;
    int coloff = (m < 3) ? m * DIMC : 0;
    int bx = blockIdx.x * 32, by = blockIdx.y * 32;
    int tx = threadIdx.x, ty = threadIdx.y;
#pragma unroll
    for (int i = 0; i < 32; i += 8)
        t[ty + i][tx] = src[(size_t)(by + ty + i) * ld + coloff + bx + tx];
    __syncthreads();
    __half* dst = g_WT + (size_t)m * DIMC * DIMC;
#pragma unroll
    for (int i = 0; i < 32; i += 8)
        dst[(size_t)(bx + ty + i) * DIMC + by + tx] = __float2half_rn(t[tx][ty + i]);
}

// ---------------- row sums of w_k / w_v ------------------------------------
__global__ void rowsum_kernel(const float* __restrict__ w_k,
                              const float* __restrict__ w_v) {
    int p = threadIdx.x;
    if (p < PP) {
        float s1 = 0.f, s2 = 0.f;
        for (int n = 0; n < N_TOK; n++) { s1 += w_k[p * N_TOK + n]; s2 += w_v[p * N_TOK + n]; }
        g_sk[p] = s1;
        g_sv[p] = s2;
    }
}

// ====== fused xproj: reads x fp32 once, emits x16 + XK + XV (all fp16) =====
#define XP_STAGE_F (16 * DIMC)
#define XP_SMEM    (2 * XP_STAGE_F * 4 + 64 * PP * 8)

__global__ __launch_bounds__(256, 2) void xproj_kernel(
    const float* __restrict__ x,
    const float* __restrict__ w_k, const float* __restrict__ w_v) {
    extern __shared__ __align__(16) char xsm[];
    float*  xs  = (float*)xsm;                          // [2][16*512]
    float2* swp = (float2*)(xsm + 2 * XP_STAGE_F * 4);  // [64][16] (wk, wv)
    uint32_t sbase = smem_u32(xsm);

    int b = blockIdx.x;
    int t = threadIdx.x;
    const float* xg = x + (size_t)b * N_TOK * DIMC;

    for (int i = t; i < N_TOK * PP; i += 256) {
        int p = i & 15, n = i >> 4;
        swp[n * PP + p] = make_float2(w_k[p * N_TOK + n], w_v[p * N_TOK + n]);
    }

    auto load_stage = [&](int s) {
        uint32_t dst = sbase + (s & 1) * (XP_STAGE_F * 4);
        const float* src = xg + (size_t)s * XP_STAGE_F;
#pragma unroll
        for (int i = 0; i < 8; i++)
            cp16(dst + t * 16 + i * 4096, src + t * 4 + i * 1024);
    };

    float2 ak[PP], av[PP];
#pragma unroll
    for (int p = 0; p < PP; p++) { ak[p] = make_float2(0.f, 0.f); av[p] = make_float2(0.f, 0.f); }

    load_stage(0); cp_commit();

    for (int s = 0; s < 4; s++) {
        if (s < 3) { load_stage(s + 1); cp_commit(); cp_wait1(); }
        else cp_wait0();
        __syncthreads();
        const float* buf = xs + (s & 1) * XP_STAGE_F;
#pragma unroll 4
        for (int nl = 0; nl < 16; nl++) {
            int n = s * 16 + nl;
            float2 xv = *(const float2*)(buf + nl * DIMC + 2 * t);
            *(__half2*)(g_x16 + ((size_t)b * N_TOK + n) * DIMC + 2 * t) =
                __floats2half2_rn(xv.x, xv.y);
            const float2* wrow = swp + n * PP;
#pragma unroll
            for (int p = 0; p < PP; p++) {
                float2 w = wrow[p];
                ak[p].x += w.x * xv.x; ak[p].y += w.x * xv.y;
                av[p].x += w.y * xv.x; av[p].y += w.y * xv.y;
            }
        }
        __syncthreads();
    }

#pragma unroll
    for (int p = 0; p < PP; p++) {
        size_t row = (size_t)b * PP + p;
        *(__half2*)(g_XK + row * DIMC + 2 * t) = __floats2half2_rn(ak[p].x, ak[p].y);
        *(__half2*)(g_XV + row * DIMC + 2 * t) = __floats2half2_rn(av[p].x, av[p].y);
    }
}

// =================== mma.sync fp16 GEMM ====================================
#define STAGEB 20480
#define DYN_SMEM (3 * STAGEB)

template <typename OutT>
__global__ __launch_bounds__(256, 2) void tgemm_kernel(
    const __half* __restrict__ A, const __half* __restrict__ Bt,
    OutT* __restrict__ C,
    const float* __restrict__ biascol, const float* __restrict__ srow, float alpha) {
    extern __shared__ __align__(16) char smem[];
    uint32_t sb = smem_u32(smem);

    int tid = threadIdx.x;
    int wid = tid >> 5, lane = tid & 31;
    int bn = blockIdx.x, bm = blockIdx.y;

    const __half* Ag = A + (size_t)bm * 128 * DIMC;
    const __half* Bg = Bt + (size_t)bn * 128 * DIMC;

    int grow = tid >> 2, gcol = tid & 3;
    auto load_stage = [&](int kc, int st) {
        uint32_t a0 = sb + st * STAGEB;
        uint32_t b0 = a0 + 10240;
        const __half* Agk = Ag + kc * 32;
        const __half* Bgk = Bg + kc * 32;
#pragma unroll
        for (int i = 0; i < 2; i++) {
            int row = grow + i * 64;
            cp16(a0 + row * 80 + gcol * 16, Agk + (size_t)row * DIMC + gcol * 8);
            cp16(b0 + row * 80 + gcol * 16, Bgk + (size_t)row * DIMC + gcol * 8);
        }
    };

    float acc[2][8][4];
#pragma unroll
    for (int mt = 0; mt < 2; mt++)
#pragma unroll
        for (int nt = 0; nt < 8; nt++)
#pragma unroll
            for (int e = 0; e < 4; e++) acc[mt][nt][e] = 0.f;

    int warp_m = wid & 3, warp_n = wid >> 2;
    int arow = (lane & 7) + ((lane >> 3) & 1) * 8;
    int achk = lane >> 4;
    int brow = (lane & 7) + ((lane >> 4) & 1) * 8;
    int bchk = (lane >> 3) & 1;

    load_stage(0, 0); cp_commit();
    load_stage(1, 1); cp_commit();

    const int NK = 16;
    for (int kc = 0; kc < NK; kc++) {
        int st = kc % 3;
        cp_wait1();
        __syncthreads();
        if (kc + 2 < NK) load_stage(kc + 2, (kc + 2) % 3);
        cp_commit();

        uint32_t aS = sb + st * STAGEB;
        uint32_t bS = aS + 10240;
#pragma unroll
        for (int ks = 0; ks < 2; ks++) {
            uint32_t af[2][4];
            uint32_t abase = aS + (uint32_t)((warp_m * 32 + arow) * 80 + ks * 32 + achk * 16);
            ldsm_x4(af[0], abase);
            ldsm_x4(af[1], abase + 16 * 80);
            uint32_t bf[8][2];
#pragma unroll
            for (int bt = 0; bt < 4; bt++) {
                uint32_t t4[4];
                ldsm_x4(t4, bS + (uint32_t)((warp_n * 64 + bt * 16 + brow) * 80 + ks * 32 + bchk * 16));
                bf[2 * bt][0] = t4[0]; bf[2 * bt][1] = t4[1];
                bf[2 * bt + 1][0] = t4[2]; bf[2 * bt + 1][1] = t4[3];
            }
#pragma unroll
            for (int mt = 0; mt < 2; mt++)
#pragma unroll
                for (int nt = 0; nt < 8; nt++)
                    mma16816(acc[mt][nt], af[mt], bf[nt]);
        }
        __syncthreads();
    }

    int rbase = bm * 128 + warp_m * 32 + (lane >> 2);
    int cbase = bn * 128 + warp_n * 64 + (lane & 3) * 2;
#pragma unroll
    for (int mt = 0; mt < 2; mt++) {
#pragma unroll
        for (int h = 0; h < 2; h++) {
            int r = rbase + mt * 16 + h * 8;
            float sr = srow ? srow[r & 15] : 1.f;
            OutT* crow = C + (size_t)r * DIMC;
#pragma unroll
            for (int nt = 0; nt < 8; nt++) {
                int c = cbase + nt * 8;
                float ox = (acc[mt][nt][h * 2 + 0] + sr * biascol[c]) * alpha;
                float oy = (acc[mt][nt][h * 2 + 1] + sr * biascol[c + 1]) * alpha;
                if constexpr (sizeof(OutT) == 2) {
                    *(__half2*)(crow + c) = __floats2half2_rn(ox, oy);
                } else {
                    *(float2*)(crow + c) = make_float2(ox, oy);
                }
            }
        }
    }
}

// ---------------- attention: fp16 in/out, fp32 math ------------------------
__global__ __launch_bounds__(256) void attn_kernel(const float* __restrict__ biastab) {
    __shared__ float skp[NH * PP * HD];
    __shared__ float svp[NH * PP * HD];
    int b = blockIdx.x;

    for (int i = threadIdx.x; i < NH * PP * HD; i += blockDim.x) {
        int h = i / (PP * HD);
        int p = (i / HD) % PP;
        int d = i % HD;
        size_t src = ((size_t)b * PP + p) * DIMC + h * HD + d;
        skp[i] = __half2float(g_KP16[src]);
        svp[i] = __half2float(g_VP16[src]);
    }
    __syncthreads();

    for (int task = threadIdx.x; task < NH * N_TOK; task += blockDim.x) {
        int h = task / N_TOK;
        int n = task % N_TOK;
        // q: all 32 halves (16 half2 words) — FIX for round-6 bug (only 16 loaded)
        const __half2* qrow2 = (const __half2*)(g_Q16 + ((size_t)b * N_TOK + n) * DIMC + h * HD);
        float q[HD];
#pragma unroll
        for (int w = 0; w < HD / 2; w++) {
            float2 f = __half22float2(qrow2[w]);
            q[2 * w] = f.x;
            q[2 * w + 1] = f.y;
        }
        int yn = n >> 3, xn = n & 7;
        float logit[PP];
#pragma unroll
        for (int p = 0; p < PP; p++) {
            const float* kr = &skp[(h * PP + p) * HD];
            float s = 0.f;
#pragma unroll
            for (int d = 0; d < HD; d++) s += q[d] * kr[d];
            int yp = p >> 3, xp = p & 7;
            int idx = (yn - yp + 7) * 15 + (xn - xp + 7);
            logit[p] = s + biastab[idx * NH + h];
        }
        float m = logit[0];
#pragma unroll
        for (int p = 1; p < PP; p++) m = fmaxf(m, logit[p]);
        float sum = 0.f;
#pragma unroll
        for (int p = 0; p < PP; p++) {
            float e = __expf(logit[p] - m);
            logit[p] = e;
            sum += e;
        }
        float inv = 1.f / sum;
        float o[HD];
#pragma unroll
        for (int d = 0; d < HD; d++) o[d] = 0.f;
#pragma unroll
        for (int p = 0; p < PP; p++) {
            float w = logit[p] * inv;
            const float* vr = &svp[(h * PP + p) * HD];
#pragma unroll
            for (int d = 0; d < HD; d++) o[d] += w * vr[d];
        }
        __half2* orow = (__half2*)(g_O16 + ((size_t)b * N_TOK + n) * DIMC + h * HD);
#pragma unroll
        for (int d = 0; d < HD; d += 2)
            orow[d >> 1] = __floats2half2_rn(o[d], o[d + 1]);
    }
}

// ---------------------------------------------------------------------------
extern "C" void kernel_launch(void* const* d_in, const int* in_sizes, int n_in,
                              void* d_out, int out_size) {
    const float* x      = (const float*)d_in[0];
    const float* w_qkv  = (const float*)d_in[1];
    const float* b_qkv  = (const float*)d_in[2];
    const float* w_proj = (const float*)d_in[3];
    const float* b_proj = (const float*)d_in[4];
    const float* w_k    = (const float*)d_in[5];
    const float* w_v    = (const float*)d_in[6];
    const float* btab   = (const float*)d_in[7];
    float* out = (float*)d_out;

    float *sk, *sv;
    __half *Q16, *x16, *XK, *XV, *KP16, *VP16, *O16, *WT;
    cudaGetSymbolAddress((void**)&Q16,  g_Q16);
    cudaGetSymbolAddress((void**)&x16,  g_x16);
    cudaGetSymbolAddress((void**)&XK,   g_XK);
    cudaGetSymbolAddress((void**)&XV,   g_XV);
    cudaGetSymbolAddress((void**)&KP16, g_KP16);
    cudaGetSymbolAddress((void**)&VP16, g_VP16);
    cudaGetSymbolAddress((void**)&O16,  g_O16);
    cudaGetSymbolAddress((void**)&WT,   g_WT);
    cudaGetSymbolAddress((void**)&sk,   g_sk);
    cudaGetSymbolAddress((void**)&sv,   g_sv);

    cudaFuncSetAttribute(tgemm_kernel<__half>, cudaFuncAttributeMaxDynamicSharedMemorySize, DYN_SMEM);
    cudaFuncSetAttribute(tgemm_kernel<float>,  cudaFuncAttributeMaxDynamicSharedMemorySize, DYN_SMEM);
    cudaFuncSetAttribute(xproj_kernel, cudaFuncAttributeMaxDynamicSharedMemorySize, XP_SMEM);

    const float scale = 0.17677669529663687f;  // 32^-0.5

    transpose_kernel<<<dim3(16, 16, 4), dim3(32, 8)>>>(w_qkv, w_proj);
    rowsum_kernel<<<1, 32>>>(w_k, w_v);
    xproj_kernel<<<B_WIN, 256, XP_SMEM>>>(x, w_k, w_v);

    // Q16 = (x @ Wq + bq) * scale
    tgemm_kernel<__half><<<dim3(4, MQ / 128), 256, DYN_SMEM>>>(
        x16, WT + 0 * DIMC * DIMC, Q16, b_qkv, nullptr, scale);
    // KP16 = XK @ Wk + s_k[p] * bk
    tgemm_kernel<__half><<<dim3(4, MP / 128), 256, DYN_SMEM>>>(
        XK, WT + 1 * DIMC * DIMC, KP16, b_qkv + DIMC, sk, 1.f);
    // VP16 = XV @ Wv + s_v[p] * bv
    tgemm_kernel<__half><<<dim3(4, MP / 128), 256, DYN_SMEM>>>(
        XV, WT + 2 * DIMC * DIMC, VP16, b_qkv + 2 * DIMC, sv, 1.f);

    attn_kernel<<<B_WIN, 256>>>(btab);

    // out = O @ w_proj + b_proj   (fp32 out)
    tgemm_kernel<float><<<dim3(4, MQ / 128), 256, DYN_SMEM>>>(
        O16, WT + 3 * DIMC * DIMC, out, b_proj, nullptr, 1.f);
}